// round 1
// baseline (speedup 1.0000x reference)
#include <cuda_runtime.h>
#include <cfloat>

// Problem constants (from reference)
#define PB 7      // pooled bins per dim
#define HH 50
#define WW 50
#define CC 512
#define BB 2
#define RR 64
#define C4 (CC / 4)   // 128 float4 per pixel

// One CTA per (b, r, py, px) output bin. 128 threads, each owns one float4
// of the 512 channels. Pooled region is at most 4x4 pixels; always >= 1x1
// and always in-bounds (proved from input ranges), so no clamping needed.
__global__ __launch_bounds__(C4) void roipool_kernel(
    const float4* __restrict__ fm,    // (B,H,W,C) as float4
    const int*    __restrict__ rois,  // (B,R,4) int32: y0,x0,h,w
    float4*       __restrict__ out)   // (B,R,P,P,C) as float4
{
    int idx = blockIdx.x;                 // b*R*P*P + r*P*P + py*P + px
    int px = idx % PB;
    int t  = idx / PB;
    int py = t % PB;
    t /= PB;
    int r = t % RR;
    int b = t / RR;

    const int* roi = rois + (b * RR + r) * 4;
    int y0 = roi[0], x0 = roi[1], h = roi[2], w = roi[3];

    // Bin bounds — fp32 arithmetic exactly as the reference:
    // step = extent/7 (fp32), start = trunc(i*step), end = trunc((i+1)*step),
    // last bin end = extent, size = max(end-start, 1).
    float stepy = (float)h / 7.0f;
    float stepx = (float)w / 7.0f;
    int ys = (int)((float)py * stepy);
    int ye = (py == PB - 1) ? h : (int)((float)(py + 1) * stepy);
    int sy = max(ye - ys, 1);
    int xs = (int)((float)px * stepx);
    int xe = (px == PB - 1) ? w : (int)((float)(px + 1) * stepx);
    int sx = max(xe - xs, 1);

    int ybase = y0 + ys;
    int xbase = x0 + xs;

    int c4 = threadIdx.x;  // 0..127
    const float4* fmb = fm + ((size_t)b * HH * WW) * C4 + c4;

    float4 m = make_float4(-FLT_MAX, -FLT_MAX, -FLT_MAX, -FLT_MAX);

    for (int dy = 0; dy < sy; ++dy) {
        const float4* rowp = fmb + (size_t)((ybase + dy) * WW + xbase) * C4;
        #pragma unroll 4
        for (int dx = 0; dx < sx; ++dx) {
            float4 v = __ldg(rowp + (size_t)dx * C4);
            m.x = fmaxf(m.x, v.x);
            m.y = fmaxf(m.y, v.y);
            m.z = fmaxf(m.z, v.z);
            m.w = fmaxf(m.w, v.w);
        }
    }

    out[(size_t)idx * C4 + c4] = m;
}

extern "C" void kernel_launch(void* const* d_in, const int* in_sizes, int n_in,
                              void* d_out, int out_size) {
    const float4* fm   = (const float4*)d_in[0];  // x_maps float32 (2,50,50,512)
    const int*    rois = (const int*)d_in[1];     // x_rois int32 (2,64,4)
    float4*       out  = (float4*)d_out;          // (2,64,7,7,512) float32

    int nblocks = BB * RR * PB * PB;  // 6272
    roipool_kernel<<<nblocks, C4>>>(fm, rois, out);
}

// round 2
// speedup vs baseline: 1.0855x; 1.0855x over previous
#include <cuda_runtime.h>
#include <cfloat>

// Problem constants (from reference)
#define PB 7      // pooled bins per dim
#define HH 50
#define WW 50
#define CC 512
#define BB 2
#define RR 64
#define C4 (CC / 4)   // 128 float4 per pixel

// One CTA per (b, r, py, px) output bin. 128 threads, each owns one float4
// of the 512 channels.
//
// Key fact: extent in [7,26)  =>  bin size sy, sx in [1,4] always, and the
// pooled window is always fully in-bounds (max index y0+h-1 <= 48 < 50).
// So the reduction is a compile-time 4x4 grid of predicated loads: 16
// independent LDG.128 with constant offsets, issued back-to-back for max
// memory-level parallelism, followed by an fmax tree.
__global__ __launch_bounds__(C4) void roipool_kernel(
    const float4* __restrict__ fm,    // (B,H,W,C) as float4
    const int*    __restrict__ rois,  // (B,R,4) int32: y0,x0,h,w
    float4*       __restrict__ out)   // (B,R,P,P,C) as float4
{
    int idx = blockIdx.x;                 // b*R*P*P + r*P*P + py*P + px
    int px = idx % PB;
    int t  = idx / PB;
    int py = t % PB;
    t /= PB;
    int r = t % RR;
    int b = t / RR;

    const int4 roi = __ldg((const int4*)(rois + (b * RR + r) * 4));
    int y0 = roi.x, x0 = roi.y, h = roi.z, w = roi.w;

    // Bin bounds — fp32 arithmetic exactly as the reference:
    // step = extent/7 (fp32), start = trunc(i*step), end = trunc((i+1)*step),
    // last bin end = extent, size = max(end-start, 1).
    float stepy = (float)h / 7.0f;
    float stepx = (float)w / 7.0f;
    int ys = (int)((float)py * stepy);
    int ye = (py == PB - 1) ? h : (int)((float)(py + 1) * stepy);
    int sy = max(ye - ys, 1);
    int xs = (int)((float)px * stepx);
    int xe = (px == PB - 1) ? w : (int)((float)(px + 1) * stepx);
    int sx = max(xe - xs, 1);

    int c4 = threadIdx.x;  // 0..127

    // Base pointer at the top-left pixel of this bin's window, this thread's
    // channel slice. All 16 candidate loads are constant offsets from here.
    const float4* p = fm
        + ((size_t)((b * HH + (y0 + ys)) * WW + (x0 + xs))) * C4
        + c4;

    float4 m = make_float4(-FLT_MAX, -FLT_MAX, -FLT_MAX, -FLT_MAX);

    #pragma unroll
    for (int dy = 0; dy < 4; ++dy) {
        #pragma unroll
        for (int dx = 0; dx < 4; ++dx) {
            if (dy < sy && dx < sx) {
                float4 v = __ldg(p + (dy * WW + dx) * C4);
                m.x = fmaxf(m.x, v.x);
                m.y = fmaxf(m.y, v.y);
                m.z = fmaxf(m.z, v.z);
                m.w = fmaxf(m.w, v.w);
            }
        }
    }

    out[(size_t)idx * C4 + c4] = m;
}

extern "C" void kernel_launch(void* const* d_in, const int* in_sizes, int n_in,
                              void* d_out, int out_size) {
    const float4* fm   = (const float4*)d_in[0];  // x_maps float32 (2,50,50,512)
    const int*    rois = (const int*)d_in[1];     // x_rois int32 (2,64,4)
    float4*       out  = (float4*)d_out;          // (2,64,7,7,512) float32

    int nblocks = BB * RR * PB * PB;  // 6272
    roipool_kernel<<<nblocks, C4>>>(fm, rois, out);
}